// round 1
// baseline (speedup 1.0000x reference)
#include <cuda_runtime.h>
#include <math.h>

#define Bb 32
#define Cc 256
#define Tt 4096
#define Kk 9
#define Hh 512

// ---- scratch (static device globals; no runtime allocation) ----
__device__ float g_yln[(size_t)Bb * Cc * Tt];        // conv+LN output (B,C,T)
__device__ float g_y1[(size_t)Bb * Hh * Tt];         // GELU(pw1) output (B,H,T)
__device__ float g_gx2[Bb * Hh];                     // sum of squares per (b,h)
__device__ float g_s[Bb * Hh];                       // GRN row scale 1 + gamma*nx
__device__ float g_biasC[Cc];                        // pw2_b + pw2_w @ beta

// ============================================================
// K1: depthwise conv1d (K=9, edge pad) + channel LayerNorm
// one block = (b, 64-wide T tile), 256 threads (one per channel)
// ============================================================
#define TTILE 64
__global__ __launch_bounds__(256) void dwconv_ln_kernel(
    const float* __restrict__ x,
    const float* __restrict__ dw_w, const float* __restrict__ dw_b,
    const float* __restrict__ ln_w, const float* __restrict__ ln_b)
{
    extern __shared__ float sm[];
    float* xs = sm;                 // [C][73]  (72 used, pad -> stride 73, conflict-free)
    float* ys = sm + Cc * 73;       // [C][65]  (64 used, pad -> stride 65)

    const int b  = blockIdx.x / (Tt / TTILE);
    const int t0 = (blockIdx.x % (Tt / TTILE)) * TTILE;
    const int tid = threadIdx.x;
    const float* xb = x + (size_t)b * Cc * Tt;

    // load input tile with edge clamp: t in [t0-4, t0+67]
    for (int idx = tid; idx < Cc * 72; idx += 256) {
        int c = idx / 72, i = idx % 72;
        int t = t0 + i - 4;
        t = min(max(t, 0), Tt - 1);
        xs[c * 73 + i] = xb[(size_t)c * Tt + t];
    }
    __syncthreads();

    // depthwise conv: thread tid owns channel c=tid
    {
        const int c = tid;
        float w[9];
#pragma unroll
        for (int k = 0; k < 9; k++) w[k] = dw_w[c * 9 + k];
        const float bias = dw_b[c];
        const float* xr = &xs[c * 73];
        float* yr = &ys[c * 65];
#pragma unroll 4
        for (int t = 0; t < TTILE; t++) {
            float v = bias;
#pragma unroll
            for (int k = 0; k < 9; k++) v = fmaf(xr[t + k], w[k], v);
            yr[t] = v;
        }
    }
    __syncthreads();

    // channel LayerNorm per t: warp handles one t, lane covers 8 channels
    const int warp = tid >> 5, lane = tid & 31;
    for (int tt = warp; tt < TTILE; tt += 8) {
        float sum = 0.f, sq = 0.f;
#pragma unroll
        for (int j = 0; j < 8; j++) {
            float v = ys[(lane + 32 * j) * 65 + tt];
            sum += v;
            sq = fmaf(v, v, sq);
        }
#pragma unroll
        for (int o = 16; o; o >>= 1) {
            sum += __shfl_xor_sync(0xffffffffu, sum, o);
            sq  += __shfl_xor_sync(0xffffffffu, sq, o);
        }
        const float mu   = sum * (1.f / Cc);
        const float var  = sq * (1.f / Cc) - mu * mu;
        const float rstd = rsqrtf(var + 1e-5f);
#pragma unroll
        for (int j = 0; j < 8; j++) {
            int c = lane + 32 * j;
            float v = ys[c * 65 + tt];
            ys[c * 65 + tt] = (v - mu) * rstd * ln_w[c] + ln_b[c];
        }
    }
    __syncthreads();

    // coalesced store (t fastest)
    float* out = g_yln + (size_t)b * Cc * Tt + t0;
    for (int idx = tid; idx < Cc * TTILE; idx += 256) {
        int c = idx / TTILE, t = idx % TTILE;
        out[(size_t)c * Tt + t] = ys[c * 65 + t];
    }
}

// ============================================================
// K2: biasC[c] = pw2_b[c] + sum_h pw2_w[c,h] * grn_beta[h]
// ============================================================
__global__ void biasc_kernel(const float* __restrict__ pw2_w,
                             const float* __restrict__ pw2_b,
                             const float* __restrict__ beta)
{
    int c = blockIdx.x * blockDim.x + threadIdx.x;
    if (c < Cc) {
        float s = pw2_b[c];
        for (int h = 0; h < Hh; h++) s = fmaf(pw2_w[c * Hh + h], beta[h], s);
        g_biasC[c] = s;
    }
}

// ============================================================
// K3: GEMM1  y1[b,m,n] = GELU( pw1_w[m,:] @ yln[b,:,n] + pw1_b[m] )
//     + fused per-row sum-of-squares accumulation into g_gx2
// 128x128x16 tile, 256 threads, 8x8 per-thread
// ============================================================
#define BM 128
#define BN 128
#define BK 16

__global__ __launch_bounds__(256) void gemm1_kernel(
    const float* __restrict__ A,       // pw1_w (H x C) row-major
    const float* __restrict__ bias)    // pw1_b (H)
{
    __shared__ float As[BK][BM];
    __shared__ float Bs[BK][BN];

    const int b  = blockIdx.z;
    const int m0 = blockIdx.y * BM;
    const int n0 = blockIdx.x * BN;
    const float* X = g_yln + (size_t)b * Cc * Tt;

    const int tid = threadIdx.x;
    const int tx = tid & 15, ty = tid >> 4;
    const int arow = tid >> 2, acol4 = tid & 3;   // A: 2 float4 per thread
    const int brow = tid >> 5, bcol4 = tid & 31;  // B: 2 float4 per thread

    float acc[8][8] = {};

    for (int k0 = 0; k0 < Cc; k0 += BK) {
#pragma unroll
        for (int r = 0; r < 2; r++) {
            int m = arow + r * 64;
            float4 a = *(const float4*)&A[(size_t)(m0 + m) * Cc + k0 + acol4 * 4];
            As[acol4 * 4 + 0][m] = a.x;
            As[acol4 * 4 + 1][m] = a.y;
            As[acol4 * 4 + 2][m] = a.z;
            As[acol4 * 4 + 3][m] = a.w;
        }
#pragma unroll
        for (int r = 0; r < 2; r++) {
            int k = brow + r * 8;
            float4 v = *(const float4*)&X[(size_t)(k0 + k) * Tt + n0 + bcol4 * 4];
            *(float4*)&Bs[k][bcol4 * 4] = v;
        }
        __syncthreads();
#pragma unroll
        for (int k = 0; k < BK; k++) {
            float rm[8], rn[8];
#pragma unroll
            for (int i = 0; i < 8; i++) rm[i] = As[k][ty * 8 + i];
#pragma unroll
            for (int j = 0; j < 8; j++) rn[j] = Bs[k][tx * 8 + j];
#pragma unroll
            for (int i = 0; i < 8; i++)
#pragma unroll
                for (int j = 0; j < 8; j++)
                    acc[i][j] = fmaf(rm[i], rn[j], acc[i][j]);
        }
        __syncthreads();
    }

    // epilogue: bias + exact GELU, store, accumulate row sum-of-squares
    float rowsq[8] = {};
    float* Y = g_y1 + (size_t)b * Hh * Tt;
#pragma unroll
    for (int i = 0; i < 8; i++) {
        int m = m0 + ty * 8 + i;
        float bm = bias[m];
#pragma unroll
        for (int j = 0; j < 8; j++) {
            int n = n0 + tx * 8 + j;
            float v = acc[i][j] + bm;
            float g = 0.5f * v * (1.0f + erff(v * 0.70710678118654752440f));
            Y[(size_t)m * Tt + n] = g;
            rowsq[i] = fmaf(g, g, rowsq[i]);
        }
    }

    __shared__ float smrow[BM];
    if (tid < BM) smrow[tid] = 0.f;
    __syncthreads();
#pragma unroll
    for (int i = 0; i < 8; i++) atomicAdd(&smrow[ty * 8 + i], rowsq[i]);
    __syncthreads();
    if (tid < BM) atomicAdd(&g_gx2[b * Hh + m0 + tid], smrow[tid]);
}

// ============================================================
// K4: GRN scales  s[b,h] = 1 + gamma[h] * gx / (mean_h(gx) + 1e-6)
// ============================================================
__global__ void grn_scale_kernel(const float* __restrict__ gamma)
{
    const int b = blockIdx.x;
    const int h = threadIdx.x;          // 512 threads
    float gx = sqrtf(g_gx2[b * Hh + h]);

    __shared__ float warpsum[16];
    __shared__ float total;
    float s = gx;
#pragma unroll
    for (int o = 16; o; o >>= 1) s += __shfl_xor_sync(0xffffffffu, s, o);
    if ((h & 31) == 0) warpsum[h >> 5] = s;
    __syncthreads();
    if (h == 0) {
        float t = 0.f;
#pragma unroll
        for (int i = 0; i < 16; i++) t += warpsum[i];
        total = t;
    }
    __syncthreads();
    const float mean = total * (1.f / Hh);
    const float nx = gx / (mean + 1e-6f);
    g_s[b * Hh + h] = 1.f + gamma[h] * nx;
}

// ============================================================
// K5: GEMM2  out[b,c,n] = x[b,c,n] + biasC[c]
//                       + sum_h pw2_w[c,h] * (y1[b,h,n] * s[b,h])
// ============================================================
__global__ __launch_bounds__(256) void gemm2_kernel(
    const float* __restrict__ A,       // pw2_w (C x H) row-major
    const float* __restrict__ x,
    float* __restrict__ out)
{
    __shared__ float As[BK][BM];
    __shared__ float Bs[BK][BN];

    const int b  = blockIdx.z;
    const int m0 = blockIdx.y * BM;
    const int n0 = blockIdx.x * BN;
    const float* X = g_y1 + (size_t)b * Hh * Tt;
    const float* sb = g_s + b * Hh;

    const int tid = threadIdx.x;
    const int tx = tid & 15, ty = tid >> 4;
    const int arow = tid >> 2, acol4 = tid & 3;
    const int brow = tid >> 5, bcol4 = tid & 31;

    float acc[8][8] = {};

    for (int k0 = 0; k0 < Hh; k0 += BK) {
#pragma unroll
        for (int r = 0; r < 2; r++) {
            int m = arow + r * 64;
            float4 a = *(const float4*)&A[(size_t)(m0 + m) * Hh + k0 + acol4 * 4];
            As[acol4 * 4 + 0][m] = a.x;
            As[acol4 * 4 + 1][m] = a.y;
            As[acol4 * 4 + 2][m] = a.z;
            As[acol4 * 4 + 3][m] = a.w;
        }
#pragma unroll
        for (int r = 0; r < 2; r++) {
            int k = brow + r * 8;
            float4 v = *(const float4*)&X[(size_t)(k0 + k) * Tt + n0 + bcol4 * 4];
            float sk = sb[k0 + k];      // GRN row scale
            v.x *= sk; v.y *= sk; v.z *= sk; v.w *= sk;
            *(float4*)&Bs[k][bcol4 * 4] = v;
        }
        __syncthreads();
#pragma unroll
        for (int k = 0; k < BK; k++) {
            float rm[8], rn[8];
#pragma unroll
            for (int i = 0; i < 8; i++) rm[i] = As[k][ty * 8 + i];
#pragma unroll
            for (int j = 0; j < 8; j++) rn[j] = Bs[k][tx * 8 + j];
#pragma unroll
            for (int i = 0; i < 8; i++)
#pragma unroll
                for (int j = 0; j < 8; j++)
                    acc[i][j] = fmaf(rm[i], rn[j], acc[i][j]);
        }
        __syncthreads();
    }

    const float* xb = x + (size_t)b * Cc * Tt;
    float* ob = out + (size_t)b * Cc * Tt;
#pragma unroll
    for (int i = 0; i < 8; i++) {
        int m = m0 + ty * 8 + i;
        float bc = g_biasC[m];
#pragma unroll
        for (int j = 0; j < 8; j++) {
            int n = n0 + tx * 8 + j;
            size_t idx = (size_t)m * Tt + n;
            ob[idx] = xb[idx] + acc[i][j] + bc;
        }
    }
}

// ============================================================
extern "C" void kernel_launch(void* const* d_in, const int* in_sizes, int n_in,
                              void* d_out, int out_size)
{
    const float* x        = (const float*)d_in[0];
    const float* dw_w     = (const float*)d_in[1];
    const float* dw_b     = (const float*)d_in[2];
    const float* ln_w     = (const float*)d_in[3];
    const float* ln_b     = (const float*)d_in[4];
    const float* pw1_w    = (const float*)d_in[5];
    const float* pw1_b    = (const float*)d_in[6];
    const float* grn_gamma= (const float*)d_in[7];
    const float* grn_beta = (const float*)d_in[8];
    const float* pw2_w    = (const float*)d_in[9];
    // pw2_b = d_in[10] used in biasc
    const float* pw2_b    = (const float*)d_in[10];
    float* out = (float*)d_out;

    // zero the gx2 accumulator (memset node is graph-capturable)
    void* gx2ptr = nullptr;
    cudaGetSymbolAddress(&gx2ptr, g_gx2);
    cudaMemsetAsync(gx2ptr, 0, Bb * Hh * sizeof(float), 0);

    // K1: conv + LN
    size_t smem1 = (size_t)(Cc * 73 + Cc * 65) * sizeof(float);   // 141,312 B
    cudaFuncSetAttribute(dwconv_ln_kernel,
                         cudaFuncAttributeMaxDynamicSharedMemorySize, (int)smem1);
    dwconv_ln_kernel<<<Bb * (Tt / TTILE), 256, smem1>>>(x, dw_w, dw_b, ln_w, ln_b);

    // K2: folded output bias (independent, cheap)
    biasc_kernel<<<1, 256>>>(pw2_w, pw2_b, grn_beta);

    // K3: GEMM1 + GELU + sumsq
    dim3 g1(Tt / BN, Hh / BM, Bb);
    gemm1_kernel<<<g1, 256>>>(pw1_w, pw1_b);

    // K4: GRN scales
    grn_scale_kernel<<<Bb, Hh>>>(grn_gamma);

    // K5: GEMM2 + residual
    dim3 g2(Tt / BN, Cc / BM, Bb);
    gemm2_kernel<<<g2, 256>>>(pw2_w, x, out);
}

// round 4
// speedup vs baseline: 3.2023x; 3.2023x over previous
#include <cuda_runtime.h>
#include <cuda_fp16.h>
#include <math.h>
#include <stdint.h>
#include <string.h>

#define Bb 32
#define Cc 256
#define Tt 4096
#define Hh 512

// ---- scratch (static device globals; no runtime allocation) ----
__device__ __half g_yln_h[(size_t)Bb * Tt * Cc];   // conv+LN output (B,T,C) fp16
__device__ __half g_y1_h[(size_t)Bb * Tt * Hh];    // GELU(pw1) output (B,T,H) fp16
__device__ __half g_w1h[(size_t)Hh * Cc];          // pw1_w fp16
__device__ __half g_w2s[(size_t)Bb * Cc * Hh];     // pw2_w * s[b,h] fp16 per batch
__device__ float  g_gx2[Bb * Hh];                  // sum of squares per (b,h)
__device__ float  g_s[Bb * Hh];                    // GRN row scale 1 + gamma*nx
__device__ float  g_biasC[Cc];                     // pw2_b + pw2_w @ beta

// ============================================================
// helpers
// ============================================================
__device__ __forceinline__ uint32_t smem_u32(const void* p) {
    uint32_t a;
    asm("{ .reg .u64 t; cvta.to.shared.u64 t, %1; cvt.u32.u64 %0, t; }" : "=r"(a) : "l"(p));
    return a;
}
__device__ __forceinline__ uint32_t swz(uint32_t off) {
    return off ^ ((off >> 3) & 0x70);
}
#define CP16(dst, src) \
    asm volatile("cp.async.cg.shared.global [%0], [%1], 16;" :: "r"(dst), \
                 "l"(__cvta_generic_to_global(src)))
#define CP_COMMIT() asm volatile("cp.async.commit_group;")
#define CP_WAIT1()  asm volatile("cp.async.wait_group 1;")
#define CP_WAIT0()  asm volatile("cp.async.wait_group 0;")

#define LDSM4(r0, r1, r2, r3, addr) \
    asm volatile("ldmatrix.sync.aligned.m8n8.x4.shared.b16 {%0,%1,%2,%3}, [%4];" \
        : "=r"(r0), "=r"(r1), "=r"(r2), "=r"(r3) : "r"(addr))

#define MMA16816(d, a, b0, b1) \
    asm volatile("mma.sync.aligned.m16n8k16.row.col.f32.f16.f16.f32 " \
        "{%0,%1,%2,%3},{%4,%5,%6,%7},{%8,%9},{%0,%1,%2,%3};" \
        : "+f"((d)[0]), "+f"((d)[1]), "+f"((d)[2]), "+f"((d)[3]) \
        : "r"((a)[0]), "r"((a)[1]), "r"((a)[2]), "r"((a)[3]), "r"(b0), "r"(b1))

// ============================================================
// K1: depthwise conv1d (K=9, edge pad) + channel LayerNorm -> (B,T,C) fp16
// ============================================================
#define TTILE 64
__global__ __launch_bounds__(256) void dwconv_ln_kernel(
    const float* __restrict__ x,
    const float* __restrict__ dw_w, const float* __restrict__ dw_b,
    const float* __restrict__ ln_w, const float* __restrict__ ln_b)
{
    extern __shared__ float sm[];
    float* xs = sm;                 // [C][73]
    float* ys = sm + Cc * 73;       // [C][65]

    const int b  = blockIdx.x / (Tt / TTILE);
    const int t0 = (blockIdx.x % (Tt / TTILE)) * TTILE;
    const int tid = threadIdx.x;
    const float* xb = x + (size_t)b * Cc * Tt;

    for (int idx = tid; idx < Cc * 72; idx += 256) {
        int c = idx / 72, i = idx % 72;
        int t = t0 + i - 4;
        t = min(max(t, 0), Tt - 1);
        xs[c * 73 + i] = xb[(size_t)c * Tt + t];
    }
    __syncthreads();

    {
        const int c = tid;
        float w[9];
#pragma unroll
        for (int k = 0; k < 9; k++) w[k] = dw_w[c * 9 + k];
        const float bias = dw_b[c];
        const float* xr = &xs[c * 73];
        float* yr = &ys[c * 65];
#pragma unroll 4
        for (int t = 0; t < TTILE; t++) {
            float v = bias;
#pragma unroll
            for (int k = 0; k < 9; k++) v = fmaf(xr[t + k], w[k], v);
            yr[t] = v;
        }
    }
    __syncthreads();

    const int warp = tid >> 5, lane = tid & 31;
    for (int tt = warp; tt < TTILE; tt += 8) {
        float sum = 0.f, sq = 0.f;
#pragma unroll
        for (int j = 0; j < 8; j++) {
            float v = ys[(lane + 32 * j) * 65 + tt];
            sum += v;
            sq = fmaf(v, v, sq);
        }
#pragma unroll
        for (int o = 16; o; o >>= 1) {
            sum += __shfl_xor_sync(0xffffffffu, sum, o);
            sq  += __shfl_xor_sync(0xffffffffu, sq, o);
        }
        const float mu   = sum * (1.f / Cc);
        const float var  = sq * (1.f / Cc) - mu * mu;
        const float rstd = rsqrtf(var + 1e-5f);
#pragma unroll
        for (int j = 0; j < 8; j++) {
            int c = lane + 32 * j;
            float v = ys[c * 65 + tt];
            ys[c * 65 + tt] = (v - mu) * rstd * ln_w[c] + ln_b[c];
        }
    }
    __syncthreads();

    __half* out = g_yln_h + (size_t)b * Tt * Cc + (size_t)t0 * Cc;
    for (int idx = tid; idx < Cc * TTILE; idx += 256) {
        int t = idx >> 8, c = idx & 255;
        out[(size_t)t * Cc + c] = __float2half_rn(ys[c * 65 + t]);
    }
}

// ============================================================
// K2a: convert pw1_w -> fp16
// ============================================================
__global__ void convert_w1_kernel(const float* __restrict__ w) {
    int i = blockIdx.x * 256 + threadIdx.x;
    g_w1h[i] = __float2half_rn(w[i]);
}

// K2b: biasC[c] = pw2_b[c] + sum_h pw2_w[c,h] * grn_beta[h]
__global__ void biasc_kernel(const float* __restrict__ pw2_w,
                             const float* __restrict__ pw2_b,
                             const float* __restrict__ beta)
{
    int c = blockIdx.x * blockDim.x + threadIdx.x;
    if (c < Cc) {
        float s = pw2_b[c];
        for (int h = 0; h < Hh; h++) s = fmaf(pw2_w[c * Hh + h], beta[h], s);
        g_biasC[c] = s;
    }
}

// ============================================================
// K3: GEMM1 (mma.sync)  D[h,t] = sum_c w1h[h,c] * yln[b,t,c]
//   epilogue: +bias, exact GELU, store (B,T,H) fp16, sumsq -> g_gx2
// CTA 256 thr, tile 128(M=h) x 128(N=t), BK=64, 2-stage cp.async
// warp w: wm=w&1 (64 rows), wn=w>>1 (32 cols); 4 m16-tiles x 4 n8-tiles
// ============================================================
#define SM1_BYTES 66048
#define SM2_BYTES 70144

__global__ __launch_bounds__(256, 2) void gemm1_mma(const float* __restrict__ pw1_b)
{
    extern __shared__ __align__(128) char smem[];
    const uint32_t sbase = smem_u32(smem);
    const int tid = threadIdx.x, lane = tid & 31, w = tid >> 5;
    const int wm = w & 1, wn = w >> 1;
    const int b = blockIdx.z, m0 = blockIdx.y * 128, n0 = blockIdx.x * 128;
    const __half* Asrc = g_w1h + (size_t)m0 * Cc;
    const __half* Bsrc = g_yln_h + (size_t)b * Tt * Cc + (size_t)n0 * Cc;
    const int KITERS = Cc / 64;   // 4

    // prologue: stages 0,1
#pragma unroll
    for (int st = 0; st < 2; st++) {
        uint32_t ab = sbase + st * 32768;
        int k0 = st * 64;
#pragma unroll
        for (int i = 0; i < 4; i++) {
            int u = tid + i * 256, row = u >> 3, cell = u & 7;
            CP16(ab + swz(row * 128 + cell * 16), Asrc + (size_t)row * Cc + k0 + cell * 8);
            CP16(ab + 16384 + swz(row * 128 + cell * 16), Bsrc + (size_t)row * Cc + k0 + cell * 8);
        }
        CP_COMMIT();
    }

    float acc[4][4][4];
#pragma unroll
    for (int i = 0; i < 4; i++)
#pragma unroll
        for (int j = 0; j < 4; j++)
#pragma unroll
            for (int k = 0; k < 4; k++) acc[i][j][k] = 0.f;

    for (int ch = 0; ch < KITERS; ch++) {
        if (ch < KITERS - 1) { CP_WAIT1(); } else { CP_WAIT0(); }
        __syncthreads();
        const uint32_t ab = sbase + (ch & 1) * 32768, bb = ab + 16384;
#pragma unroll
        for (int k16 = 0; k16 < 4; k16++) {
            uint32_t aF[4][4];
            const int acolb = k16 * 32 + (lane >> 4) * 16;
#pragma unroll
            for (int mt = 0; mt < 4; mt++) {
                int row = wm * 64 + mt * 16 + (lane & 15);
                LDSM4(aF[mt][0], aF[mt][1], aF[mt][2], aF[mt][3], ab + swz(row * 128 + acolb));
            }
            uint32_t bF[4][2];
            const int brl = ((lane >> 4) << 3) + (lane & 7);
            const int bcolb = k16 * 32 + ((lane >> 3) & 1) * 16;
#pragma unroll
            for (int np = 0; np < 2; np++) {
                int row = wn * 32 + np * 16 + brl;
                uint32_t r0, r1, r2, r3;
                LDSM4(r0, r1, r2, r3, bb + swz(row * 128 + bcolb));
                bF[np * 2 + 0][0] = r0; bF[np * 2 + 0][1] = r1;
                bF[np * 2 + 1][0] = r2; bF[np * 2 + 1][1] = r3;
            }
#pragma unroll
            for (int mt = 0; mt < 4; mt++)
#pragma unroll
                for (int nt = 0; nt < 4; nt++)
                    MMA16816(acc[mt][nt], aF[mt], bF[nt][0], bF[nt][1]);
        }
        __syncthreads();
        if (ch + 2 < KITERS) {
            uint32_t ab2 = sbase + (ch & 1) * 32768;
            int k0 = (ch + 2) * 64;
#pragma unroll
            for (int i = 0; i < 4; i++) {
                int u = tid + i * 256, row = u >> 3, cell = u & 7;
                CP16(ab2 + swz(row * 128 + cell * 16), Asrc + (size_t)row * Cc + k0 + cell * 8);
                CP16(ab2 + 16384 + swz(row * 128 + cell * 16), Bsrc + (size_t)row * Cc + k0 + cell * 8);
            }
            CP_COMMIT();
        }
    }

    // epilogue: GELU + stage [t][h] fp16 (stride 136) + row sumsq
    __half* stg = (__half*)smem;                    // [128][136]
    float* rowsq = (float*)(smem + 34816);          // 128 floats
    if (tid < 128) rowsq[tid] = 0.f;
    __syncthreads();

#pragma unroll
    for (int mt = 0; mt < 4; mt++) {
        const int r1 = wm * 64 + mt * 16 + (lane >> 2);
        const int r2 = r1 + 8;
        const float bias1 = __ldg(&pw1_b[m0 + r1]);
        const float bias2 = __ldg(&pw1_b[m0 + r2]);
        float sq1 = 0.f, sq2 = 0.f;
#pragma unroll
        for (int nt = 0; nt < 4; nt++) {
            const int n = wn * 32 + nt * 8 + 2 * (lane & 3);
#pragma unroll
            for (int cc = 0; cc < 2; cc++) {
                float v = acc[mt][nt][cc] + bias1;
                float g = 0.5f * v * (1.0f + erff(v * 0.70710678118654752440f));
                sq1 = fmaf(g, g, sq1);
                stg[(n + cc) * 136 + r1] = __float2half_rn(g);
                float v2 = acc[mt][nt][cc + 2] + bias2;
                float g2 = 0.5f * v2 * (1.0f + erff(v2 * 0.70710678118654752440f));
                sq2 = fmaf(g2, g2, sq2);
                stg[(n + cc) * 136 + r2] = __float2half_rn(g2);
            }
        }
        atomicAdd(&rowsq[r1], sq1);
        atomicAdd(&rowsq[r2], sq2);
    }
    __syncthreads();

    // copy out: rows = t, 128 halves each
    __half* Y = g_y1_h + (size_t)b * Tt * Hh;
    for (int i = tid; i < 128 * 16; i += 256) {
        int rowt = i >> 4, seg = i & 15;
        uint4 v = *(uint4*)&stg[rowt * 136 + seg * 8];
        *(uint4*)&Y[(size_t)(n0 + rowt) * Hh + m0 + seg * 8] = v;
    }
    if (tid < 128) atomicAdd(&g_gx2[b * Hh + m0 + tid], rowsq[tid]);
}

// ============================================================
// K4: GRN scales
// ============================================================
__global__ void grn_scale_kernel(const float* __restrict__ gamma)
{
    const int b = blockIdx.x;
    const int h = threadIdx.x;
    float gx = sqrtf(g_gx2[b * Hh + h]);

    __shared__ float warpsum[16];
    __shared__ float total;
    float s = gx;
#pragma unroll
    for (int o = 16; o; o >>= 1) s += __shfl_xor_sync(0xffffffffu, s, o);
    if ((h & 31) == 0) warpsum[h >> 5] = s;
    __syncthreads();
    if (h == 0) {
        float t = 0.f;
#pragma unroll
        for (int i = 0; i < 16; i++) t += warpsum[i];
        total = t;
    }
    __syncthreads();
    const float mean = total * (1.f / Hh);
    const float nx = gx / (mean + 1e-6f);
    g_s[b * Hh + h] = 1.f + gamma[h] * nx;
}

// K4b: g_w2s[b,c,h] = w2[c,h] * s[b,h]  (fp16)
__global__ void scale_w2_kernel(const float* __restrict__ w2)
{
    int i = blockIdx.x * 256 + threadIdx.x;       // over Bb*Cc*Hh
    int b = i >> 17;                               // Cc*Hh = 131072
    int r = i & 131071;
    int h = r & 511;
    g_w2s[i] = __float2half_rn(w2[r] * g_s[(b << 9) + h]);
}

// ============================================================
// K5: GEMM2 (mma.sync)  D[c,t] = sum_h w2s[b,c,h] * y1[b,t,h]
//   epilogue: + x + biasC -> out (B,C,T) fp32
// ============================================================
__global__ __launch_bounds__(256, 2) void gemm2_mma(
    const float* __restrict__ x, float* __restrict__ out)
{
    extern __shared__ __align__(128) char smem[];
    const uint32_t sbase = smem_u32(smem);
    const int tid = threadIdx.x, lane = tid & 31, w = tid >> 5;
    const int wm = w & 1, wn = w >> 1;
    const int b = blockIdx.z, m0 = blockIdx.y * 128, n0 = blockIdx.x * 128;
    const __half* Asrc = g_w2s + (size_t)b * Cc * Hh + (size_t)m0 * Hh;
    const __half* Bsrc = g_y1_h + (size_t)b * Tt * Hh + (size_t)n0 * Hh;
    const int KITERS = Hh / 64;    // 8

#pragma unroll
    for (int st = 0; st < 2; st++) {
        uint32_t ab = sbase + st * 32768;
        int k0 = st * 64;
#pragma unroll
        for (int i = 0; i < 4; i++) {
            int u = tid + i * 256, row = u >> 3, cell = u & 7;
            CP16(ab + swz(row * 128 + cell * 16), Asrc + (size_t)row * Hh + k0 + cell * 8);
            CP16(ab + 16384 + swz(row * 128 + cell * 16), Bsrc + (size_t)row * Hh + k0 + cell * 8);
        }
        CP_COMMIT();
    }

    float acc[4][4][4];
#pragma unroll
    for (int i = 0; i < 4; i++)
#pragma unroll
        for (int j = 0; j < 4; j++)
#pragma unroll
            for (int k = 0; k < 4; k++) acc[i][j][k] = 0.f;

    for (int ch = 0; ch < KITERS; ch++) {
        if (ch < KITERS - 1) { CP_WAIT1(); } else { CP_WAIT0(); }
        __syncthreads();
        const uint32_t ab = sbase + (ch & 1) * 32768, bb = ab + 16384;
#pragma unroll
        for (int k16 = 0; k16 < 4; k16++) {
            uint32_t aF[4][4];
            const int acolb = k16 * 32 + (lane >> 4) * 16;
#pragma unroll
            for (int mt = 0; mt < 4; mt++) {
                int row = wm * 64 + mt * 16 + (lane & 15);
                LDSM4(aF[mt][0], aF[mt][1], aF[mt][2], aF[mt][3], ab + swz(row * 128 + acolb));
            }
            uint32_t bF[4][2];
            const int brl = ((lane >> 4) << 3) + (lane & 7);
            const int bcolb = k16 * 32 + ((lane >> 3) & 1) * 16;
#pragma unroll
            for (int np = 0; np < 2; np++) {
                int row = wn * 32 + np * 16 + brl;
                uint32_t r0, r1, r2, r3;
                LDSM4(r0, r1, r2, r3, bb + swz(row * 128 + bcolb));
                bF[np * 2 + 0][0] = r0; bF[np * 2 + 0][1] = r1;
                bF[np * 2 + 1][0] = r2; bF[np * 2 + 1][1] = r3;
            }
#pragma unroll
            for (int mt = 0; mt < 4; mt++)
#pragma unroll
                for (int nt = 0; nt < 4; nt++)
                    MMA16816(acc[mt][nt], aF[mt], bF[nt][0], bF[nt][1]);
        }
        __syncthreads();
        if (ch + 2 < KITERS) {
            uint32_t ab2 = sbase + (ch & 1) * 32768;
            int k0 = (ch + 2) * 64;
#pragma unroll
            for (int i = 0; i < 4; i++) {
                int u = tid + i * 256, row = u >> 3, cell = u & 7;
                CP16(ab2 + swz(row * 128 + cell * 16), Asrc + (size_t)row * Hh + k0 + cell * 8);
                CP16(ab2 + 16384 + swz(row * 128 + cell * 16), Bsrc + (size_t)row * Hh + k0 + cell * 8);
            }
            CP_COMMIT();
        }
    }

    // epilogue: stage fp32 [c][t] stride 136, add biasC; then + x, store
    float* stg = (float*)smem;     // [128][136] floats = 69632 B
    __syncthreads();
#pragma unroll
    for (int mt = 0; mt < 4; mt++) {
        const int r1 = wm * 64 + mt * 16 + (lane >> 2);
        const int r2 = r1 + 8;
        const float bc1 = g_biasC[m0 + r1];
        const float bc2 = g_biasC[m0 + r2];
#pragma unroll
        for (int nt = 0; nt < 4; nt++) {
            const int n = wn * 32 + nt * 8 + 2 * (lane & 3);
            float2 v1 = make_float2(acc[mt][nt][0] + bc1, acc[mt][nt][1] + bc1);
            float2 v2 = make_float2(acc[mt][nt][2] + bc2, acc[mt][nt][3] + bc2);
            *(float2*)&stg[r1 * 136 + n] = v1;
            *(float2*)&stg[r2 * 136 + n] = v2;
        }
    }
    __syncthreads();

    const float* xb = x + (size_t)b * Cc * Tt;
    float* ob = out + (size_t)b * Cc * Tt;
    for (int i = tid; i < 128 * 32; i += 256) {
        int row = i >> 5, seg = i & 31;
        float4 v = *(float4*)&stg[row * 136 + seg * 4];
        size_t o = (size_t)(m0 + row) * Tt + n0 + seg * 4;
        float4 xv = *(const float4*)&xb[o];
        v.x += xv.x; v.y += xv.y; v.z += xv.z; v.w += xv.w;
        *(float4*)&ob[o] = v;
    }
}

// ============================================================
extern "C" void kernel_launch(void* const* d_in, const int* in_sizes, int n_in,
                              void* d_out, int out_size)
{
    const float* x        = (const float*)d_in[0];
    const float* dw_w     = (const float*)d_in[1];
    const float* dw_b     = (const float*)d_in[2];
    const float* ln_w     = (const float*)d_in[3];
    const float* ln_b     = (const float*)d_in[4];
    const float* pw1_w    = (const float*)d_in[5];
    const float* pw1_b    = (const float*)d_in[6];
    const float* grn_gamma= (const float*)d_in[7];
    const float* grn_beta = (const float*)d_in[8];
    const float* pw2_w    = (const float*)d_in[9];
    const float* pw2_b    = (const float*)d_in[10];
    float* out = (float*)d_out;

    void* gx2ptr = nullptr;
    cudaGetSymbolAddress(&gx2ptr, g_gx2);
    cudaMemsetAsync(gx2ptr, 0, Bb * Hh * sizeof(float), 0);

    // K1: conv + LN -> fp16 (B,T,C)
    size_t smem1 = (size_t)(Cc * 73 + Cc * 65) * sizeof(float);
    cudaFuncSetAttribute(dwconv_ln_kernel,
                         cudaFuncAttributeMaxDynamicSharedMemorySize, (int)smem1);
    dwconv_ln_kernel<<<Bb * (Tt / TTILE), 256, smem1>>>(x, dw_w, dw_b, ln_w, ln_b);

    convert_w1_kernel<<<(Hh * Cc) / 256, 256>>>(pw1_w);
    biasc_kernel<<<1, 256>>>(pw2_w, pw2_b, grn_beta);

    // K3: GEMM1
    cudaFuncSetAttribute(gemm1_mma, cudaFuncAttributeMaxDynamicSharedMemorySize, SM1_BYTES);
    dim3 g1(Tt / 128, Hh / 128, Bb);
    gemm1_mma<<<g1, 256, SM1_BYTES>>>(pw1_b);

    // K4: GRN scales, then scaled W2
    grn_scale_kernel<<<Bb, Hh>>>(grn_gamma);
    scale_w2_kernel<<<(Bb * Cc * Hh) / 256, 256>>>(pw2_w);

    // K5: GEMM2 + residual
    cudaFuncSetAttribute(gemm2_mma, cudaFuncAttributeMaxDynamicSharedMemorySize, SM2_BYTES);
    dim3 g2(Tt / 128, Cc / 128, Bb);
    gemm2_mma<<<g2, 256, SM2_BYTES>>>(x, out);
}

// round 5
// speedup vs baseline: 4.1700x; 1.3022x over previous
#include <cuda_runtime.h>
#include <cuda_fp16.h>
#include <math.h>
#include <stdint.h>
#include <string.h>

#define Bb 32
#define Cc 256
#define Tt 4096
#define Hh 512

// ---- scratch (static device globals; no runtime allocation) ----
__device__ __half g_yln_h[(size_t)Bb * Tt * Cc];   // conv+LN output (B,T,C) fp16
__device__ __half g_y1_h[(size_t)Bb * Tt * Hh];    // GELU(pw1) output (B,T,H) fp16
__device__ __half g_w1h[(size_t)Hh * Cc];          // pw1_w fp16
__device__ __half g_w2s[(size_t)Bb * Cc * Hh];     // pw2_w * s[b,h] fp16 per batch
__device__ float  g_gx2[Bb * Hh];                  // sum of squares per (b,h)
__device__ float  g_s[Bb * Hh];                    // GRN row scale 1 + gamma*nx
__device__ float  g_biasC[Cc];                     // pw2_b + pw2_w @ beta

// ============================================================
// helpers
// ============================================================
__device__ __forceinline__ uint32_t smem_u32(const void* p) {
    uint32_t a;
    asm("{ .reg .u64 t; cvta.to.shared.u64 t, %1; cvt.u32.u64 %0, t; }" : "=r"(a) : "l"(p));
    return a;
}
__device__ __forceinline__ uint32_t swz(uint32_t off) {
    return off ^ ((off >> 3) & 0x70);
}
#define CP16(dst, src) \
    asm volatile("cp.async.cg.shared.global [%0], [%1], 16;" :: "r"(dst), \
                 "l"(__cvta_generic_to_global(src)))
#define CP_COMMIT() asm volatile("cp.async.commit_group;")
#define CP_WAIT1()  asm volatile("cp.async.wait_group 1;")
#define CP_WAIT0()  asm volatile("cp.async.wait_group 0;")

#define LDSM4(r0, r1, r2, r3, addr) \
    asm volatile("ldmatrix.sync.aligned.m8n8.x4.shared.b16 {%0,%1,%2,%3}, [%4];" \
        : "=r"(r0), "=r"(r1), "=r"(r2), "=r"(r3) : "r"(addr))

#define MMA16816(d, a, b0, b1) \
    asm volatile("mma.sync.aligned.m16n8k16.row.col.f32.f16.f16.f32 " \
        "{%0,%1,%2,%3},{%4,%5,%6,%7},{%8,%9},{%0,%1,%2,%3};" \
        : "+f"((d)[0]), "+f"((d)[1]), "+f"((d)[2]), "+f"((d)[3]) \
        : "r"((a)[0]), "r"((a)[1]), "r"((a)[2]), "r"((a)[3]), "r"(b0), "r"(b1))

// ============================================================
// shared GEMM mainloop: 128x128 tile, BK=64, 2-stage cp.async,
// precomputed swizzle bases (XOR addressing), acc[4][4][4]
// ============================================================
template<int LD, int KITERS>
__device__ __forceinline__ void mma_mainloop(
    const __half* __restrict__ Asrc, const __half* __restrict__ Bsrc,
    uint32_t sbase, int tid, int lane, int wm, int wn, float acc[4][4][4])
{
    // cp.async slots (4 per operand per thread)
    uint32_t dstA[4], dstB[4];
    const __half* srcA[4];
    const __half* srcB[4];
#pragma unroll
    for (int i = 0; i < 4; i++) {
        int u = tid + i * 256, row = u >> 3, cell = u & 7;
        uint32_t d = swz(row * 128 + cell * 16);
        dstA[i] = sbase + d;
        dstB[i] = sbase + 16384 + d;
        srcA[i] = Asrc + (size_t)row * LD + cell * 8;
        srcB[i] = Bsrc + (size_t)row * LD + cell * 8;
    }

    // prologue: stages 0,1 (after this, src* point at chunk 2)
#pragma unroll
    for (int st = 0; st < 2; st++) {
        const uint32_t bo = st * 32768u;
#pragma unroll
        for (int i = 0; i < 4; i++) {
            CP16(dstA[i] + bo, srcA[i]);
            CP16(dstB[i] + bo, srcB[i]);
            srcA[i] += 64; srcB[i] += 64;
        }
        CP_COMMIT();
    }

    // ldmatrix base registers: addr = (base + bufoff) ^ (k16*32)
    uint32_t aB[4], bB[2];
#pragma unroll
    for (int mt = 0; mt < 4; mt++) {
        int row = wm * 64 + mt * 16 + (lane & 15);
        aB[mt] = sbase + row * 128 + ((((uint32_t)row & 7) << 4) ^ (((uint32_t)lane >> 4) << 4));
    }
    {
        const int brl = ((lane >> 4) << 3) + (lane & 7);
#pragma unroll
        for (int np = 0; np < 2; np++) {
            int row = wn * 32 + np * 16 + brl;
            bB[np] = sbase + 16384 + row * 128 +
                     ((((uint32_t)row & 7) << 4) ^ ((((uint32_t)lane >> 3) & 1) << 4));
        }
    }

    for (int ch = 0; ch < KITERS; ch++) {
        if (ch < KITERS - 1) { CP_WAIT1(); } else { CP_WAIT0(); }
        __syncthreads();
        const uint32_t bo = (ch & 1) * 32768u;
        const uint32_t a0 = aB[0] + bo, a1 = aB[1] + bo, a2 = aB[2] + bo, a3 = aB[3] + bo;
        const uint32_t b0 = bB[0] + bo, b1 = bB[1] + bo;
#pragma unroll
        for (int k16 = 0; k16 < 4; k16++) {
            const uint32_t kx = (uint32_t)k16 * 32u;
            uint32_t aF[4][4];
            LDSM4(aF[0][0], aF[0][1], aF[0][2], aF[0][3], a0 ^ kx);
            LDSM4(aF[1][0], aF[1][1], aF[1][2], aF[1][3], a1 ^ kx);
            LDSM4(aF[2][0], aF[2][1], aF[2][2], aF[2][3], a2 ^ kx);
            LDSM4(aF[3][0], aF[3][1], aF[3][2], aF[3][3], a3 ^ kx);
            uint32_t bF[4][2];
            {
                uint32_t r0, r1, r2, r3;
                LDSM4(r0, r1, r2, r3, b0 ^ kx);
                bF[0][0] = r0; bF[0][1] = r1; bF[1][0] = r2; bF[1][1] = r3;
                LDSM4(r0, r1, r2, r3, b1 ^ kx);
                bF[2][0] = r0; bF[2][1] = r1; bF[3][0] = r2; bF[3][1] = r3;
            }
#pragma unroll
            for (int mt = 0; mt < 4; mt++)
#pragma unroll
                for (int nt = 0; nt < 4; nt++)
                    MMA16816(acc[mt][nt], aF[mt], bF[nt][0], bF[nt][1]);
        }
        __syncthreads();
        if (ch + 2 < KITERS) {
            const uint32_t bo2 = (ch & 1) * 32768u;
#pragma unroll
            for (int i = 0; i < 4; i++) {
                CP16(dstA[i] + bo2, srcA[i]);
                CP16(dstB[i] + bo2, srcB[i]);
                srcA[i] += 64; srcB[i] += 64;
            }
            CP_COMMIT();
        }
    }
}

// ============================================================
// K1: depthwise conv1d (K=9, edge pad) + channel LayerNorm -> (B,T,C) fp16
// in-place conv in xs [C][73]; smem 74.7KB -> 3 CTAs/SM
// ============================================================
#define TTILE 64
__global__ __launch_bounds__(256) void dwconv_ln_kernel(
    const float* __restrict__ x,
    const float* __restrict__ dw_w, const float* __restrict__ dw_b,
    const float* __restrict__ ln_w, const float* __restrict__ ln_b)
{
    extern __shared__ float sm[];
    float* xs = sm;                 // [C][73] (72 loaded; conv result lands in [0..63])

    const int b  = blockIdx.x / (Tt / TTILE);
    const int t0 = (blockIdx.x % (Tt / TTILE)) * TTILE;
    const int tid = threadIdx.x;
    const float* xb = x + (size_t)b * Cc * Tt;

    for (int idx = tid; idx < Cc * 72; idx += 256) {
        int c = idx / 72, i = idx % 72;
        int t = t0 + i - 4;
        t = min(max(t, 0), Tt - 1);
        xs[c * 73 + i] = xb[(size_t)c * Tt + t];
    }
    __syncthreads();

    {
        const int c = tid;
        float w[9];
#pragma unroll
        for (int k = 0; k < 9; k++) w[k] = dw_w[c * 9 + k];
        const float bias = dw_b[c];
        float* xr = &xs[c * 73];
#pragma unroll 4
        for (int t = 0; t < TTILE; t++) {
            float v = bias;
#pragma unroll
            for (int k = 0; k < 9; k++) v = fmaf(xr[t + k], w[k], v);
            xr[t] = v;   // in-place: slot t is never read again (windows move forward)
        }
    }
    __syncthreads();

    const int warp = tid >> 5, lane = tid & 31;
    for (int tt = warp; tt < TTILE; tt += 8) {
        float sum = 0.f, sq = 0.f;
#pragma unroll
        for (int j = 0; j < 8; j++) {
            float v = xs[(lane + 32 * j) * 73 + tt];
            sum += v;
            sq = fmaf(v, v, sq);
        }
#pragma unroll
        for (int o = 16; o; o >>= 1) {
            sum += __shfl_xor_sync(0xffffffffu, sum, o);
            sq  += __shfl_xor_sync(0xffffffffu, sq, o);
        }
        const float mu   = sum * (1.f / Cc);
        const float var  = sq * (1.f / Cc) - mu * mu;
        const float rstd = rsqrtf(var + 1e-5f);
#pragma unroll
        for (int j = 0; j < 8; j++) {
            int c = lane + 32 * j;
            float v = xs[c * 73 + tt];
            xs[c * 73 + tt] = (v - mu) * rstd * ln_w[c] + ln_b[c];
        }
    }
    __syncthreads();

    // store (B,T,C) fp16, half2-vectorized (c fastest)
    __half2* out2 = (__half2*)(g_yln_h + (size_t)b * Tt * Cc + (size_t)t0 * Cc);
    for (int idx = tid; idx < (Cc / 2) * TTILE; idx += 256) {
        int t = idx >> 7, c2 = (idx & 127) * 2;
        out2[(size_t)t * (Cc / 2) + (c2 >> 1)] =
            __floats2half2_rn(xs[c2 * 73 + t], xs[(c2 + 1) * 73 + t]);
    }
}

// ============================================================
// K2a: convert pw1_w -> fp16
// ============================================================
__global__ void convert_w1_kernel(const float* __restrict__ w) {
    int i = blockIdx.x * 256 + threadIdx.x;
    g_w1h[i] = __float2half_rn(w[i]);
}

// K2b: biasC[c] = pw2_b[c] + sum_h pw2_w[c,h] * grn_beta[h]
__global__ void biasc_kernel(const float* __restrict__ pw2_w,
                             const float* __restrict__ pw2_b,
                             const float* __restrict__ beta)
{
    int c = blockIdx.x * blockDim.x + threadIdx.x;
    if (c < Cc) {
        float s = pw2_b[c];
        for (int h = 0; h < Hh; h++) s = fmaf(pw2_w[c * Hh + h], beta[h], s);
        g_biasC[c] = s;
    }
}

// ============================================================
// K3: GEMM1  D[h,t] = sum_c w1h[h,c] * yln[b,t,c]
//   epilogue: +bias, exact GELU, store (B,T,H) fp16, sumsq -> g_gx2
// ============================================================
#define SM1_BYTES 66048
#define SM2_BYTES 70144

__global__ __launch_bounds__(256, 2) void gemm1_mma(const float* __restrict__ pw1_b)
{
    extern __shared__ __align__(128) char smem[];
    const uint32_t sbase = smem_u32(smem);
    const int tid = threadIdx.x, lane = tid & 31, w = tid >> 5;
    const int wm = w & 1, wn = w >> 1;
    const int b = blockIdx.z, m0 = blockIdx.y * 128, n0 = blockIdx.x * 128;

    float acc[4][4][4];
#pragma unroll
    for (int i = 0; i < 4; i++)
#pragma unroll
        for (int j = 0; j < 4; j++)
#pragma unroll
            for (int k = 0; k < 4; k++) acc[i][j][k] = 0.f;

    mma_mainloop<Cc, Cc / 64>(
        g_w1h + (size_t)m0 * Cc,
        g_yln_h + (size_t)b * Tt * Cc + (size_t)n0 * Cc,
        sbase, tid, lane, wm, wn, acc);

    // epilogue: GELU + stage [t][h] fp16 (stride 136) + row sumsq
    __half* stg = (__half*)smem;                    // [128][136]
    float* rowsq = (float*)(smem + 34816);          // 128 floats
    if (tid < 128) rowsq[tid] = 0.f;
    __syncthreads();

#pragma unroll
    for (int mt = 0; mt < 4; mt++) {
        const int r1 = wm * 64 + mt * 16 + (lane >> 2);
        const int r2 = r1 + 8;
        const float bias1 = __ldg(&pw1_b[m0 + r1]);
        const float bias2 = __ldg(&pw1_b[m0 + r2]);
        float sq1 = 0.f, sq2 = 0.f;
#pragma unroll
        for (int nt = 0; nt < 4; nt++) {
            const int n = wn * 32 + nt * 8 + 2 * (lane & 3);
#pragma unroll
            for (int cc = 0; cc < 2; cc++) {
                float v = acc[mt][nt][cc] + bias1;
                float g = 0.5f * v * (1.0f + erff(v * 0.70710678118654752440f));
                sq1 = fmaf(g, g, sq1);
                stg[(n + cc) * 136 + r1] = __float2half_rn(g);
                float v2 = acc[mt][nt][cc + 2] + bias2;
                float g2 = 0.5f * v2 * (1.0f + erff(v2 * 0.70710678118654752440f));
                sq2 = fmaf(g2, g2, sq2);
                stg[(n + cc) * 136 + r2] = __float2half_rn(g2);
            }
        }
        atomicAdd(&rowsq[r1], sq1);
        atomicAdd(&rowsq[r2], sq2);
    }
    __syncthreads();

    __half* Y = g_y1_h + (size_t)b * Tt * Hh;
    for (int i = tid; i < 128 * 16; i += 256) {
        int rowt = i >> 4, seg = i & 15;
        uint4 v = *(uint4*)&stg[rowt * 136 + seg * 8];
        *(uint4*)&Y[(size_t)(n0 + rowt) * Hh + m0 + seg * 8] = v;
    }
    if (tid < 128) atomicAdd(&g_gx2[b * Hh + m0 + tid], rowsq[tid]);
}

// ============================================================
// K4: GRN scales
// ============================================================
__global__ void grn_scale_kernel(const float* __restrict__ gamma)
{
    const int b = blockIdx.x;
    const int h = threadIdx.x;
    float gx = sqrtf(g_gx2[b * Hh + h]);

    __shared__ float warpsum[16];
    __shared__ float total;
    float s = gx;
#pragma unroll
    for (int o = 16; o; o >>= 1) s += __shfl_xor_sync(0xffffffffu, s, o);
    if ((h & 31) == 0) warpsum[h >> 5] = s;
    __syncthreads();
    if (h == 0) {
        float t = 0.f;
#pragma unroll
        for (int i = 0; i < 16; i++) t += warpsum[i];
        total = t;
    }
    __syncthreads();
    const float mean = total * (1.f / Hh);
    const float nx = gx / (mean + 1e-6f);
    g_s[b * Hh + h] = 1.f + gamma[h] * nx;
}

// K4b: g_w2s[b,c,h] = w2[c,h] * s[b,h]  (fp16)
__global__ void scale_w2_kernel(const float* __restrict__ w2)
{
    int i = blockIdx.x * 256 + threadIdx.x;
    int b = i >> 17;
    int r = i & 131071;
    int h = r & 511;
    g_w2s[i] = __float2half_rn(w2[r] * g_s[(b << 9) + h]);
}

// ============================================================
// K5: GEMM2  D[c,t] = sum_h w2s[b,c,h] * y1[b,t,h]
//   epilogue: + x + biasC -> out (B,C,T) fp32
// ============================================================
__global__ __launch_bounds__(256, 2) void gemm2_mma(
    const float* __restrict__ x, float* __restrict__ out)
{
    extern __shared__ __align__(128) char smem[];
    const uint32_t sbase = smem_u32(smem);
    const int tid = threadIdx.x, lane = tid & 31, w = tid >> 5;
    const int wm = w & 1, wn = w >> 1;
    const int b = blockIdx.z, m0 = blockIdx.y * 128, n0 = blockIdx.x * 128;

    float acc[4][4][4];
#pragma unroll
    for (int i = 0; i < 4; i++)
#pragma unroll
        for (int j = 0; j < 4; j++)
#pragma unroll
            for (int k = 0; k < 4; k++) acc[i][j][k] = 0.f;

    mma_mainloop<Hh, Hh / 64>(
        g_w2s + (size_t)b * Cc * Hh + (size_t)m0 * Hh,
        g_y1_h + (size_t)b * Tt * Hh + (size_t)n0 * Hh,
        sbase, tid, lane, wm, wn, acc);

    // epilogue: stage fp32 [c][t] stride 136, add biasC; then + x, store
    float* stg = (float*)smem;     // [128][136] floats
    __syncthreads();
#pragma unroll
    for (int mt = 0; mt < 4; mt++) {
        const int r1 = wm * 64 + mt * 16 + (lane >> 2);
        const int r2 = r1 + 8;
        const float bc1 = g_biasC[m0 + r1];
        const float bc2 = g_biasC[m0 + r2];
#pragma unroll
        for (int nt = 0; nt < 4; nt++) {
            const int n = wn * 32 + nt * 8 + 2 * (lane & 3);
            float2 v1 = make_float2(acc[mt][nt][0] + bc1, acc[mt][nt][1] + bc1);
            float2 v2 = make_float2(acc[mt][nt][2] + bc2, acc[mt][nt][3] + bc2);
            *(float2*)&stg[r1 * 136 + n] = v1;
            *(float2*)&stg[r2 * 136 + n] = v2;
        }
    }
    __syncthreads();

    const float* xb = x + (size_t)b * Cc * Tt;
    float* ob = out + (size_t)b * Cc * Tt;
    for (int i = tid; i < 128 * 32; i += 256) {
        int row = i >> 5, seg = i & 31;
        float4 v = *(float4*)&stg[row * 136 + seg * 4];
        size_t o = (size_t)(m0 + row) * Tt + n0 + seg * 4;
        float4 xv = *(const float4*)&xb[o];
        v.x += xv.x; v.y += xv.y; v.z += xv.z; v.w += xv.w;
        *(float4*)&ob[o] = v;
    }
}

// ============================================================
extern "C" void kernel_launch(void* const* d_in, const int* in_sizes, int n_in,
                              void* d_out, int out_size)
{
    const float* x        = (const float*)d_in[0];
    const float* dw_w     = (const float*)d_in[1];
    const float* dw_b     = (const float*)d_in[2];
    const float* ln_w     = (const float*)d_in[3];
    const float* ln_b     = (const float*)d_in[4];
    const float* pw1_w    = (const float*)d_in[5];
    const float* pw1_b    = (const float*)d_in[6];
    const float* grn_gamma= (const float*)d_in[7];
    const float* grn_beta = (const float*)d_in[8];
    const float* pw2_w    = (const float*)d_in[9];
    const float* pw2_b    = (const float*)d_in[10];
    float* out = (float*)d_out;

    void* gx2ptr = nullptr;
    cudaGetSymbolAddress(&gx2ptr, g_gx2);
    cudaMemsetAsync(gx2ptr, 0, Bb * Hh * sizeof(float), 0);

    // K1: conv + LN -> fp16 (B,T,C)
    size_t smem1 = (size_t)(Cc * 73) * sizeof(float);   // 74,752 B
    cudaFuncSetAttribute(dwconv_ln_kernel,
                         cudaFuncAttributeMaxDynamicSharedMemorySize, (int)smem1);
    dwconv_ln_kernel<<<Bb * (Tt / TTILE), 256, smem1>>>(x, dw_w, dw_b, ln_w, ln_b);

    convert_w1_kernel<<<(Hh * Cc) / 256, 256>>>(pw1_w);
    biasc_kernel<<<1, 256>>>(pw2_w, pw2_b, grn_beta);

    // K3: GEMM1
    cudaFuncSetAttribute(gemm1_mma, cudaFuncAttributeMaxDynamicSharedMemorySize, SM1_BYTES);
    dim3 g1(Tt / 128, Hh / 128, Bb);
    gemm1_mma<<<g1, 256, SM1_BYTES>>>(pw1_b);

    // K4: GRN scales, then scaled W2
    grn_scale_kernel<<<Bb, Hh>>>(grn_gamma);
    scale_w2_kernel<<<(Bb * Cc * Hh) / 256, 256>>>(pw2_w);

    // K5: GEMM2 + residual
    cudaFuncSetAttribute(gemm2_mma, cudaFuncAttributeMaxDynamicSharedMemorySize, SM2_BYTES);
    dim3 g2(Tt / 128, Cc / 128, Bb);
    gemm2_mma<<<g2, 256, SM2_BYTES>>>(x, out);
}